// round 13
// baseline (speedup 1.0000x reference)
#include <cuda_runtime.h>
#include <cstdint>
#include <math.h>

#define HIDDEN 512
#define HEADS  8
#define DK     64
#define BATCH  2
#define NSEQ   2048
#define MROWS  (BATCH*NSEQ)     // 4096
#define BHN    (BATCH*HEADS)    // 16
#define NORMC  0.125f
#define TK     32               // keys per attention tile
#define KSPLIT 4                // key-range splits
#define NTILE_S (NSEQ/TK/KSPLIT)   // 16 key tiles per split CTA

typedef unsigned long long ull;
typedef unsigned int uint32;

// ---- packed f32x2 helpers (Blackwell FFMA2 path) ----
__device__ __forceinline__ ull bcast2(float x) {
    ull r; asm("mov.b64 %0, {%1,%1};" : "=l"(r) : "f"(x)); return r;
}
__device__ __forceinline__ float2 unpack2(ull v) {
    float2 f; asm("mov.b64 {%0,%1}, %2;" : "=f"(f.x), "=f"(f.y) : "l"(v)); return f;
}
__device__ __forceinline__ ull ffma2(ull a, ull b, ull c) {
    ull d; asm("fma.rn.f32x2 %0, %1, %2, %3;" : "=l"(d) : "l"(a), "l"(b), "l"(c)); return d;
}
__device__ __forceinline__ ull as_ull(float2 v) {
    ull r; asm("mov.b64 %0, {%1,%2};" : "=l"(r) : "f"(v.x), "f"(v.y)); return r;
}
__device__ __forceinline__ uint32 smem_u32(const void* p) {
    return (uint32)__cvta_generic_to_shared(p);
}
__device__ __forceinline__ void cpa16(uint32 dst, const void* src) {
    asm volatile("cp.async.cg.shared.global [%0], [%1], 16;" :: "r"(dst), "l"(src));
}
#define CPA_COMMIT() asm volatile("cp.async.commit_group;")
#define CPA_WAIT(n)  asm volatile("cp.async.wait_group %0;" :: "n"(n))

// Scratch: Q/K/V in [b,h,n,d] layout, complex interleaved (16B-aligned).
__device__ float4 g_q[(size_t)BHN * NSEQ * DK / 2];
__device__ float4 g_k[(size_t)BHN * NSEQ * DK / 2];
__device__ float4 g_v[(size_t)BHN * NSEQ * DK / 2];
// Split-KV partials: raw O (float4-aligned for vector stores) and denominators.
__device__ float4 g_po[(size_t)KSPLIT * BHN * NSEQ * DK / 2];
__device__ float  g_pden[(size_t)KSPLIT * BHN * NSEQ];

// ---------------------------------------------------------------------------
// Projection: Y = X @ W^T + b (complex). A stored PRE-DUPLICATED in smem
// (ax,ax,ay,ay) so the inner loop has zero broadcast MOVs:
// per kk: 4 LDS.128 + 4 LDS.64 + 32 FFMA2  (80% issue ceiling, was 67%)
// ---------------------------------------------------------------------------
__global__ __launch_bounds__(256, 2) void proj_kernel(
    const float* __restrict__ xr, const float* __restrict__ xi,
    const float* __restrict__ Wqr, const float* __restrict__ Wqi,
    const float* __restrict__ bqr, const float* __restrict__ bqi,
    const float* __restrict__ Wkr, const float* __restrict__ Wki,
    const float* __restrict__ bkr, const float* __restrict__ bki,
    const float* __restrict__ Wvr, const float* __restrict__ Wvi,
    const float* __restrict__ bvr, const float* __restrict__ bvi)
{
    __shared__ float4 Asc[64][17];   // duplicated (ax,ax,ay,ay)
    __shared__ float2 Bsc[64][17];   // packed (wr,wi)

    const int which = blockIdx.z;
    const float* Wr = (which == 0) ? Wqr : ((which == 1) ? Wkr : Wvr);
    const float* Wi = (which == 0) ? Wqi : ((which == 1) ? Wki : Wvi);
    const float* br = (which == 0) ? bqr : ((which == 1) ? bkr : bvr);
    const float* bi = (which == 0) ? bqi : ((which == 1) ? bki : bvi);
    float2* out = (float2*)((which == 0) ? g_q : ((which == 1) ? g_k : g_v));

    const int n0 = blockIdx.x * 64;
    const int m0 = blockIdx.y * 64;
    const int tid = threadIdx.x;
    const int tx = tid & 15, ty = tid >> 4;

    const int kk_s = tid & 15;
    const int rr0  = tid >> 4;

    float2 ra[4], rb[4];
    #pragma unroll
    for (int l = 0; l < 4; l++) {
        int rr = rr0 + l * 16;
        size_t ga = (size_t)(m0 + rr) * HIDDEN + kk_s;
        size_t gb = (size_t)(n0 + rr) * HIDDEN + kk_s;
        ra[l] = make_float2(xr[ga], xi[ga]);
        rb[l] = make_float2(Wr[gb], Wi[gb]);
    }

    ull acc1[4][4], acc2[4][4];
    #pragma unroll
    for (int i = 0; i < 4; i++)
        #pragma unroll
        for (int j = 0; j < 4; j++) { acc1[i][j] = 0ULL; acc2[i][j] = 0ULL; }

    for (int k0 = 0; k0 < HIDDEN; k0 += 16) {
        #pragma unroll
        for (int l = 0; l < 4; l++) {
            Asc[rr0 + l*16][kk_s] = make_float4(ra[l].x, ra[l].x, ra[l].y, ra[l].y);
            Bsc[rr0 + l*16][kk_s] = rb[l];
        }
        __syncthreads();

        if (k0 + 16 < HIDDEN) {
            #pragma unroll
            for (int l = 0; l < 4; l++) {
                int rr = rr0 + l * 16;
                size_t ga = (size_t)(m0 + rr) * HIDDEN + k0 + 16 + kk_s;
                size_t gb = (size_t)(n0 + rr) * HIDDEN + k0 + 16 + kk_s;
                ra[l] = make_float2(xr[ga], xi[ga]);
                rb[l] = make_float2(Wr[gb], Wi[gb]);
            }
        }

        #pragma unroll
        for (int kk = 0; kk < 16; kk++) {
            ull arr[4], aii[4], w2[4];
            #pragma unroll
            for (int i = 0; i < 4; i++) {
                longlong2 a = *(const longlong2*)&Asc[ty + 16*i][kk];
                arr[i] = (ull)a.x; aii[i] = (ull)a.y;
            }
            #pragma unroll
            for (int j = 0; j < 4; j++) w2[j] = as_ull(Bsc[tx + 16*j][kk]);
            #pragma unroll
            for (int i = 0; i < 4; i++)
                #pragma unroll
                for (int j = 0; j < 4; j++) {
                    acc1[i][j] = ffma2(arr[i], w2[j], acc1[i][j]);
                    acc2[i][j] = ffma2(aii[i], w2[j], acc2[i][j]);
                }
        }
        __syncthreads();
    }

    #pragma unroll
    for (int i = 0; i < 4; i++) {
        int m = m0 + ty + 16*i;
        int bb = m >> 11;
        int n  = m & 2047;
        #pragma unroll
        for (int j = 0; j < 4; j++) {
            int col = n0 + tx + 16*j;
            int h = col >> 6, d = col & 63;
            float2 c1 = unpack2(acc1[i][j]), c2 = unpack2(acc2[i][j]);
            float yr = c1.x - c2.y + br[col];
            float yi = c1.y + c2.x + bi[col];
            out[(((size_t)bb * HEADS + h) * NSEQ + n) * DK + d] = make_float2(yr, yi);
        }
    }
}

// ---------------------------------------------------------------------------
// Attention partial (split-KV), 8x1 micro-tile:
//   lane (0..31) = key within tile AND output dim-pair; warp wy (0..7) owns
//   query rows {wy+8i}. Q loads are warp-uniform broadcasts. K xor-swizzled
//   [32][32] float4 (no pad, conflict-free). P stored duplicated (w,w),
//   warp-local -> __syncwarp only between exp and PV.
// S per dp (2 dims): 1 LDS.128(K) +1 XOR +4 MOV +8 LDS.128(Q,bcast) +32 FFMA2
// PV per c: 1 LDS.128(V) + 8 LDS.64(P,bcast) + 16 FFMA2
// SMEM: Qs 32768 | Ks 2x16384 | Vs 2x16384 | Psd 16384 = 114688 (2 CTAs/SM)
// ---------------------------------------------------------------------------
#define ATTN_SMEM (32768 + 32768 + 32768 + 16384)

__global__ __launch_bounds__(256, 2) void attn_partial_kernel()
{
    extern __shared__ float smem[];
    float4* Qs  = (float4*)smem;           // [64][32] packed complex pairs
    float4* Ks  = Qs + 2048;               // [2][32][32] xor-swizzled
    float4* Vs  = Ks + 2048;               // [2][32][32] linear
    float2* Psd = (float2*)(Vs + 2048);    // [64][32] duplicated weights

    const int bh = blockIdx.y;
    const int n0 = blockIdx.x * 64;
    const int sp = blockIdx.z;
    const int tid = threadIdx.x;
    const int lane = tid & 31, wy = tid >> 5;

    const float4* qb4 = g_q + ((size_t)bh * NSEQ + n0) * 32;
    const float4* kb4 = g_k + (size_t)bh * NSEQ * 32 + (size_t)sp * NTILE_S * 1024;
    const float4* vb4 = g_v + (size_t)bh * NSEQ * 32 + (size_t)sp * NTILE_S * 1024;

    const uint32 qs_b = smem_u32(Qs);
    const uint32 ks_b = smem_u32(Ks);
    const uint32 vs_b = smem_u32(Vs);

    // Prologue: Q (32KB) + tile 0 K/V
    #pragma unroll
    for (int l = 0; l < 8; l++) {
        int id = tid + l * 256;
        cpa16(qs_b + id * 16, qb4 + id);
    }
    #pragma unroll
    for (int l = 0; l < 4; l++) {
        int id = tid + l * 256;
        int row = id >> 5, dp = id & 31;        // row: warp-uniform, dp = lane
        cpa16(ks_b + (row * 32 + (dp ^ row)) * 16, kb4 + id);
        cpa16(vs_b + id * 16, vb4 + id);
    }
    CPA_COMMIT();

    ull o0[8], o1[8];
    #pragma unroll
    for (int i = 0; i < 8; i++) { o0[i] = 0ULL; o1[i] = 0ULL; }
    float den[8] = {};

    for (int t = 0; t < NTILE_S; t++) {
        const int cur = t & 1;
        if (t + 1 < NTILE_S) {
            const int nb = cur ^ 1;
            const float4* kt = kb4 + (size_t)(t + 1) * 1024;
            const float4* vt = vb4 + (size_t)(t + 1) * 1024;
            #pragma unroll
            for (int l = 0; l < 4; l++) {
                int id = tid + l * 256;
                int row = id >> 5, dp = id & 31;
                cpa16(ks_b + (nb * 16384) + (row * 32 + (dp ^ row)) * 16, kt + id);
                cpa16(vs_b + (nb * 16384) + id * 16, vt + id);
            }
            CPA_COMMIT();
            CPA_WAIT(1);
        } else {
            CPA_WAIT(0);
        }
        __syncthreads();

        // ---- S = Q . K^T over 32 keys (my key = lane) ----
        ull s1a[8], s2a[8];
        #pragma unroll
        for (int i = 0; i < 8; i++) { s1a[i] = 0ULL; s2a[i] = 0ULL; }

        const longlong2* Ksc = (const longlong2*)Ks + cur * 1024;
        const longlong2* Qsc = (const longlong2*)Qs;

        #pragma unroll 2
        for (int dp = 0; dp < 32; dp++) {
            longlong2 kv = Ksc[lane * 32 + (dp ^ lane)];
            float2 k0 = unpack2((ull)kv.x), k1 = unpack2((ull)kv.y);
            ull kxx0 = bcast2(k0.x), kyy0 = bcast2(k0.y);
            ull kxx1 = bcast2(k1.x), kyy1 = bcast2(k1.y);
            #pragma unroll
            for (int i = 0; i < 8; i++) {
                longlong2 q2 = Qsc[(wy + 8*i) * 32 + dp];   // warp-uniform bcast
                s1a[i] = ffma2((ull)q2.x, kxx0, s1a[i]);
                s2a[i] = ffma2((ull)q2.x, kyy0, s2a[i]);
                s1a[i] = ffma2((ull)q2.y, kxx1, s1a[i]);
                s2a[i] = ffma2((ull)q2.y, kyy1, s2a[i]);
            }
        }

        // ---- w = exp(|s|*NORM): duplicated into Psd (warp-local) ----
        #pragma unroll
        for (int i = 0; i < 8; i++) {
            float2 c1 = unpack2(s1a[i]), c2 = unpack2(s2a[i]);
            float sr = c1.x - c2.y;
            float si = c1.y + c2.x;
            float w = __expf(sqrtf(sr * sr + si * si) * NORMC);
            den[i] += w;
            Psd[(wy + 8*i) * 32 + lane] = make_float2(w, w);
        }
        __syncwarp();

        // ---- O += P @ V (my dims = 2*lane, 2*lane+1) ----
        const float4* Vsc = Vs + cur * 1024;
        #pragma unroll 2
        for (int c = 0; c < 32; c++) {
            longlong2 vv = *(const longlong2*)&Vsc[c * 32 + lane];
            #pragma unroll
            for (int i = 0; i < 8; i++) {
                ull p = as_ull(Psd[(wy + 8*i) * 32 + c]);   // warp-uniform bcast
                o0[i] = ffma2(p, (ull)vv.x, o0[i]);
                o1[i] = ffma2(p, (ull)vv.y, o1[i]);
            }
        }
        __syncthreads();
    }

    // ---- denominator: warp shuffle reduce (rows are warp-local) ----
    #pragma unroll
    for (int i = 0; i < 8; i++) {
        float d = den[i];
        d += __shfl_xor_sync(0xffffffffu, d, 16);
        d += __shfl_xor_sync(0xffffffffu, d, 8);
        d += __shfl_xor_sync(0xffffffffu, d, 4);
        d += __shfl_xor_sync(0xffffffffu, d, 2);
        d += __shfl_xor_sync(0xffffffffu, d, 1);
        den[i] = d;
    }

    float4* po = g_po + (((size_t)sp * BHN + bh) * NSEQ + n0) * 32;
    float*  pd = g_pden + ((size_t)sp * BHN + bh) * NSEQ + n0;

    #pragma unroll
    for (int i = 0; i < 8; i++) {
        int nl = wy + 8*i;
        if (lane == 0) pd[nl] = den[i];
        float2 a = unpack2(o0[i]), b = unpack2(o1[i]);
        po[(size_t)nl * 32 + lane] = make_float4(a.x, a.y, b.x, b.y);
    }
}

// ---------------------------------------------------------------------------
// Combine: out = sum_s o_s / sum_s den_s. Output layout [B,N,D,2].
// ---------------------------------------------------------------------------
__global__ __launch_bounds__(256) void reduce_kernel(float* __restrict__ out)
{
    const size_t idx = (size_t)blockIdx.x * 256 + threadIdx.x;   // complex elem
    const int d  = idx & 63;
    const int h  = (int)((idx >> 6) & 7);
    const int n  = (int)((idx >> 9) & 2047);
    const int b  = (int)(idx >> 20);
    const int bh = b * HEADS + h;

    const float2* po2 = (const float2*)g_po;
    float2 o = make_float2(0.f, 0.f);
    float dsum = 0.f;
    #pragma unroll
    for (int s = 0; s < KSPLIT; s++) {
        float2 p = po2[(((size_t)s * BHN + bh) * NSEQ + n) * DK + d];
        o.x += p.x; o.y += p.y;
        dsum += g_pden[((size_t)s * BHN + bh) * NSEQ + n];
    }
    float inv = 1.0f / dsum;
    ((float2*)out)[idx] = make_float2(o.x * inv, o.y * inv);
}

extern "C" void kernel_launch(void* const* d_in, const int* in_sizes, int n_in,
                              void* d_out, int out_size)
{
    const float* xr  = (const float*)d_in[0];
    const float* xi  = (const float*)d_in[1];
    const float* Wqr = (const float*)d_in[2];
    const float* Wqi = (const float*)d_in[3];
    const float* bqr = (const float*)d_in[4];
    const float* bqi = (const float*)d_in[5];
    const float* Wkr = (const float*)d_in[6];
    const float* Wki = (const float*)d_in[7];
    const float* bkr = (const float*)d_in[8];
    const float* bki = (const float*)d_in[9];
    const float* Wvr = (const float*)d_in[10];
    const float* Wvi = (const float*)d_in[11];
    const float* bvr = (const float*)d_in[12];
    const float* bvi = (const float*)d_in[13];

    cudaFuncSetAttribute(attn_partial_kernel,
                         cudaFuncAttributeMaxDynamicSharedMemorySize, ATTN_SMEM);

    dim3 pb(256), pg(HIDDEN / 64, MROWS / 64, 3);  // (8, 64, 3)
    proj_kernel<<<pg, pb>>>(xr, xi,
                            Wqr, Wqi, bqr, bqi,
                            Wkr, Wki, bkr, bki,
                            Wvr, Wvi, bvr, bvi);

    dim3 ag(NSEQ / 64, BHN, KSPLIT);               // (32, 16, 4) = 2048 CTAs
    attn_partial_kernel<<<ag, 256, ATTN_SMEM>>>();

    const size_t n_complex = (size_t)MROWS * HIDDEN;          // 2M
    reduce_kernel<<<(unsigned)(n_complex / 256), 256>>>((float*)d_out);
}

// round 14
// speedup vs baseline: 1.1363x; 1.1363x over previous
#include <cuda_runtime.h>
#include <cstdint>
#include <math.h>

#define HIDDEN 512
#define HEADS  8
#define DK     64
#define BATCH  2
#define NSEQ   2048
#define MROWS  (BATCH*NSEQ)     // 4096
#define BHN    (BATCH*HEADS)    // 16
#define NORMC  0.125f
#define TK     32               // keys per attention tile
#define KSPLIT 4                // key-range splits
#define NTILE_S (NSEQ/TK/KSPLIT)   // 16 key tiles per split CTA

typedef unsigned long long ull;
typedef unsigned int uint32;

// ---- packed f32x2 helpers (Blackwell FFMA2 path) ----
__device__ __forceinline__ ull bcast2(float x) {
    ull r; asm("mov.b64 %0, {%1,%1};" : "=l"(r) : "f"(x)); return r;
}
__device__ __forceinline__ float2 unpack2(ull v) {
    float2 f; asm("mov.b64 {%0,%1}, %2;" : "=f"(f.x), "=f"(f.y) : "l"(v)); return f;
}
__device__ __forceinline__ ull ffma2(ull a, ull b, ull c) {
    ull d; asm("fma.rn.f32x2 %0, %1, %2, %3;" : "=l"(d) : "l"(a), "l"(b), "l"(c)); return d;
}
__device__ __forceinline__ ull as_ull(float2 v) {
    ull r; asm("mov.b64 %0, {%1,%2};" : "=l"(r) : "f"(v.x), "f"(v.y)); return r;
}
__device__ __forceinline__ uint32 smem_u32(const void* p) {
    return (uint32)__cvta_generic_to_shared(p);
}
__device__ __forceinline__ void cpa16(uint32 dst, const void* src) {
    asm volatile("cp.async.cg.shared.global [%0], [%1], 16;" :: "r"(dst), "l"(src));
}
#define CPA_COMMIT() asm volatile("cp.async.commit_group;")
#define CPA_WAIT(n)  asm volatile("cp.async.wait_group %0;" :: "n"(n))

// Scratch: Q/K/V in [b,h,n,d] layout, complex interleaved (16B-aligned).
__device__ float4 g_q[(size_t)BHN * NSEQ * DK / 2];
__device__ float4 g_k[(size_t)BHN * NSEQ * DK / 2];
__device__ float4 g_v[(size_t)BHN * NSEQ * DK / 2];
// Split-KV partials: raw O and denominators.
__device__ float4 g_po[(size_t)KSPLIT * BHN * NSEQ * DK / 2];
__device__ float  g_pden[(size_t)KSPLIT * BHN * NSEQ];

// ---------------------------------------------------------------------------
// Projection: Y = X @ W^T + b (complex), FFMA2 inner loop. R11 layout
// (float2 smem, conflict-free 2r-mod-32 banks) + SMEM PING-PONG:
// one __syncthreads per k-tile (was two).
// ---------------------------------------------------------------------------
__global__ __launch_bounds__(256, 2) void proj_kernel(
    const float* __restrict__ xr, const float* __restrict__ xi,
    const float* __restrict__ Wqr, const float* __restrict__ Wqi,
    const float* __restrict__ bqr, const float* __restrict__ bqi,
    const float* __restrict__ Wkr, const float* __restrict__ Wki,
    const float* __restrict__ bkr, const float* __restrict__ bki,
    const float* __restrict__ Wvr, const float* __restrict__ Wvi,
    const float* __restrict__ bvr, const float* __restrict__ bvi)
{
    __shared__ float2 Asc[2][64][17];
    __shared__ float2 Bsc[2][64][17];

    const int which = blockIdx.z;
    const float* Wr = (which == 0) ? Wqr : ((which == 1) ? Wkr : Wvr);
    const float* Wi = (which == 0) ? Wqi : ((which == 1) ? Wki : Wvi);
    const float* br = (which == 0) ? bqr : ((which == 1) ? bkr : bvr);
    const float* bi = (which == 0) ? bqi : ((which == 1) ? bki : bvi);
    float2* out = (float2*)((which == 0) ? g_q : ((which == 1) ? g_k : g_v));

    const int n0 = blockIdx.x * 64;
    const int m0 = blockIdx.y * 64;
    const int tid = threadIdx.x;
    const int tx = tid & 15, ty = tid >> 4;

    const int kk_s = tid & 15;
    const int rr0  = tid >> 4;

    float2 ra[4], rb[4];
    #pragma unroll
    for (int l = 0; l < 4; l++) {
        int rr = rr0 + l * 16;
        size_t ga = (size_t)(m0 + rr) * HIDDEN + kk_s;
        size_t gb = (size_t)(n0 + rr) * HIDDEN + kk_s;
        ra[l] = make_float2(xr[ga], xi[ga]);
        rb[l] = make_float2(Wr[gb], Wi[gb]);
    }
    #pragma unroll
    for (int l = 0; l < 4; l++) {
        Asc[0][rr0 + l*16][kk_s] = ra[l];
        Bsc[0][rr0 + l*16][kk_s] = rb[l];
    }

    ull acc1[4][4], acc2[4][4];
    #pragma unroll
    for (int i = 0; i < 4; i++)
        #pragma unroll
        for (int j = 0; j < 4; j++) { acc1[i][j] = 0ULL; acc2[i][j] = 0ULL; }

    #pragma unroll 1
    for (int t = 0; t < HIDDEN / 16; t++) {
        const int cur = t & 1;
        __syncthreads();   // buf[cur] stores visible; prior reads of buf[cur^1] done

        const bool more = (t + 1 < HIDDEN / 16);
        if (more) {
            const int k1 = (t + 1) * 16;
            #pragma unroll
            for (int l = 0; l < 4; l++) {
                int rr = rr0 + l * 16;
                size_t ga = (size_t)(m0 + rr) * HIDDEN + k1 + kk_s;
                size_t gb = (size_t)(n0 + rr) * HIDDEN + k1 + kk_s;
                ra[l] = make_float2(xr[ga], xi[ga]);
                rb[l] = make_float2(Wr[gb], Wi[gb]);
            }
        }

        #pragma unroll
        for (int kk = 0; kk < 16; kk++) {
            ull arr[4], aii[4], w2[4];
            #pragma unroll
            for (int i = 0; i < 4; i++) {
                float2 a = Asc[cur][ty + 16*i][kk];
                arr[i] = bcast2(a.x); aii[i] = bcast2(a.y);
            }
            #pragma unroll
            for (int j = 0; j < 4; j++) w2[j] = as_ull(Bsc[cur][tx + 16*j][kk]);
            #pragma unroll
            for (int i = 0; i < 4; i++)
                #pragma unroll
                for (int j = 0; j < 4; j++) {
                    acc1[i][j] = ffma2(arr[i], w2[j], acc1[i][j]);
                    acc2[i][j] = ffma2(aii[i], w2[j], acc2[i][j]);
                }
        }

        if (more) {
            const int nb = cur ^ 1;
            #pragma unroll
            for (int l = 0; l < 4; l++) {
                Asc[nb][rr0 + l*16][kk_s] = ra[l];
                Bsc[nb][rr0 + l*16][kk_s] = rb[l];
            }
        }
    }

    #pragma unroll
    for (int i = 0; i < 4; i++) {
        int m = m0 + ty + 16*i;
        int bb = m >> 11;
        int n  = m & 2047;
        #pragma unroll
        for (int j = 0; j < 4; j++) {
            int col = n0 + tx + 16*j;
            int h = col >> 6, d = col & 63;
            float2 c1 = unpack2(acc1[i][j]), c2 = unpack2(acc2[i][j]);
            float yr = c1.x - c2.y + br[col];
            float yi = c1.y + c2.x + bi[col];
            out[(((size_t)bb * HEADS + h) * NSEQ + n) * DK + d] = make_float2(yr, yi);
        }
    }
}

// ---------------------------------------------------------------------------
// Attention partial (split-KV) — R11 version (calibrated at ~1010us total).
// CTA = 64 queries x 512 keys of one (b,h); 32-key tiles, cp.async double
// buffering, 4x4/4x2 micro-tiles, 2 CTAs/SM.
// ---------------------------------------------------------------------------
#define KS_STRIDE 33
#define KS_BUF    (32*KS_STRIDE)
#define VS_BUF    (32*64)
#define VS_BUF_BYTES (VS_BUF*8)
#define ATTN_SMEM (32768 + 33792 + 32768 + 8448)

__global__ __launch_bounds__(256, 2) void attn_partial_kernel()
{
    extern __shared__ float smem[];
    float4* Qs = (float4*)smem;                    // [64][32]
    float4* Ks = Qs + 64*32;                       // [2][32][KS_STRIDE]
    float2* Vs = (float2*)(Ks + 2*KS_BUF);         // [2][32][64]
    float*  Ps = (float*)(Vs + 2*VS_BUF);          // [64][33]

    const int bh = blockIdx.y;
    const int n0 = blockIdx.x * 64;
    const int sp = blockIdx.z;
    const int tid = threadIdx.x;
    const int tx = tid & 15, ty = tid >> 4;

    const float4* qb4 = g_q + ((size_t)bh * NSEQ + n0) * (DK/2);
    const float4* kb4 = g_k + (size_t)bh * NSEQ * (DK/2) + (size_t)sp * NTILE_S * 1024;
    const float4* vb4 = g_v + (size_t)bh * NSEQ * (DK/2) + (size_t)sp * NTILE_S * 1024;

    const uint32 qs_b = smem_u32(Qs);
    const uint32 ks_b = smem_u32(Ks);
    const uint32 vs_b = smem_u32(Vs);

    #pragma unroll
    for (int l = 0; l < 8; l++) {
        int id = tid + l * 256;
        cpa16(qs_b + id * 16, qb4 + id);
    }
    #pragma unroll
    for (int l = 0; l < 4; l++) {
        int id = tid + l * 256;
        int row = id >> 5, dp = id & 31;
        cpa16(ks_b + (row * KS_STRIDE + dp) * 16, kb4 + row * 32 + dp);
        cpa16(vs_b + id * 16, vb4 + id);
    }
    CPA_COMMIT();

    ull o_acc[4][4];
    #pragma unroll
    for (int i = 0; i < 4; i++)
        #pragma unroll
        for (int j = 0; j < 4; j++) o_acc[i][j] = 0ULL;
    float den[4] = {};

    for (int t = 0; t < NTILE_S; t++) {
        const int cur = t & 1;
        if (t + 1 < NTILE_S) {
            const int nb = cur ^ 1;
            const float4* kt = kb4 + (size_t)(t + 1) * 1024;
            const float4* vt = vb4 + (size_t)(t + 1) * 1024;
            #pragma unroll
            for (int l = 0; l < 4; l++) {
                int id = tid + l * 256;
                int row = id >> 5, dp = id & 31;
                cpa16(ks_b + (nb * KS_BUF + row * KS_STRIDE + dp) * 16, kt + row * 32 + dp);
                cpa16(vs_b + nb * VS_BUF_BYTES + id * 16, vt + id);
            }
            CPA_COMMIT();
            CPA_WAIT(1);
        } else {
            CPA_WAIT(0);
        }
        __syncthreads();

        ull s1[4][2], s2[4][2];
        #pragma unroll
        for (int i = 0; i < 4; i++)
            #pragma unroll
            for (int j = 0; j < 2; j++) { s1[i][j] = 0ULL; s2[i][j] = 0ULL; }

        const longlong2* Ksc = (const longlong2*)(Ks + cur * KS_BUF);
        const longlong2* Qsc = (const longlong2*)Qs;

        #pragma unroll 4
        for (int dp = 0; dp < 32; dp++) {
            longlong2 q2[4];
            #pragma unroll
            for (int i = 0; i < 4; i++) q2[i] = Qsc[(ty + 16*i) * 32 + dp];

            ull kxx[2][2], kyy[2][2];
            #pragma unroll
            for (int j = 0; j < 2; j++) {
                longlong2 kv = Ksc[(tx + 16*j) * KS_STRIDE + dp];
                float2 k0 = unpack2((ull)kv.x), k1 = unpack2((ull)kv.y);
                kxx[j][0] = bcast2(k0.x); kyy[j][0] = bcast2(k0.y);
                kxx[j][1] = bcast2(k1.x); kyy[j][1] = bcast2(k1.y);
            }
            #pragma unroll
            for (int i = 0; i < 4; i++)
                #pragma unroll
                for (int j = 0; j < 2; j++) {
                    s1[i][j] = ffma2((ull)q2[i].x, kxx[j][0], s1[i][j]);
                    s2[i][j] = ffma2((ull)q2[i].x, kyy[j][0], s2[i][j]);
                    s1[i][j] = ffma2((ull)q2[i].y, kxx[j][1], s1[i][j]);
                    s2[i][j] = ffma2((ull)q2[i].y, kyy[j][1], s2[i][j]);
                }
        }

        #pragma unroll
        for (int i = 0; i < 4; i++)
            #pragma unroll
            for (int j = 0; j < 2; j++) {
                float2 c1 = unpack2(s1[i][j]), c2 = unpack2(s2[i][j]);
                float sr = c1.x - c2.y;
                float si = c1.y + c2.x;
                float a = sqrtf(sr * sr + si * si) * NORMC;
                float w = __expf(a);
                den[i] += w;
                Ps[(ty + 16*i) * 33 + (tx + 16*j)] = w;
            }
        __syncthreads();

        const float2* Vsc = Vs + cur * VS_BUF;
        #pragma unroll 4
        for (int c = 0; c < 32; c++) {
            ull p2[4], vv[4];
            #pragma unroll
            for (int i = 0; i < 4; i++) p2[i] = bcast2(Ps[(ty + 16*i) * 33 + c]);
            #pragma unroll
            for (int j = 0; j < 4; j++) vv[j] = as_ull(Vsc[c * 64 + tx + 16*j]);
            #pragma unroll
            for (int i = 0; i < 4; i++)
                #pragma unroll
                for (int j = 0; j < 4; j++)
                    o_acc[i][j] = ffma2(p2[i], vv[j], o_acc[i][j]);
        }
        __syncthreads();
    }

    #pragma unroll
    for (int i = 0; i < 4; i++) Ps[(ty + 16*i) * 17 + tx] = den[i];
    __syncthreads();
    #pragma unroll
    for (int i = 0; i < 4; i++) {
        float s = 0.f;
        #pragma unroll
        for (int tt = 0; tt < 16; tt++) s += Ps[(ty + 16*i) * 17 + tt];
        den[i] = s;
    }

    float2* po = (float2*)g_po + (((size_t)sp * BHN + bh) * NSEQ + n0) * DK;
    float*  pd = g_pden + ((size_t)sp * BHN + bh) * NSEQ + n0;

    #pragma unroll
    for (int i = 0; i < 4; i++) {
        int nl = ty + 16*i;
        if (tx == 0) pd[nl] = den[i];
        #pragma unroll
        for (int j = 0; j < 4; j++) {
            int d = tx + 16*j;
            po[(size_t)nl * DK + d] = unpack2(o_acc[i][j]);
        }
    }
}

// ---------------------------------------------------------------------------
// Combine: out = sum_s o_s / sum_s den_s. Output layout [B,N,D,2].
// ---------------------------------------------------------------------------
__global__ __launch_bounds__(256) void reduce_kernel(float* __restrict__ out)
{
    const size_t idx = (size_t)blockIdx.x * 256 + threadIdx.x;
    const int d  = idx & 63;
    const int h  = (int)((idx >> 6) & 7);
    const int n  = (int)((idx >> 9) & 2047);
    const int b  = (int)(idx >> 20);
    const int bh = b * HEADS + h;

    const float2* po2 = (const float2*)g_po;
    float2 o = make_float2(0.f, 0.f);
    float dsum = 0.f;
    #pragma unroll
    for (int s = 0; s < KSPLIT; s++) {
        float2 p = po2[(((size_t)s * BHN + bh) * NSEQ + n) * DK + d];
        o.x += p.x; o.y += p.y;
        dsum += g_pden[((size_t)s * BHN + bh) * NSEQ + n];
    }
    float inv = 1.0f / dsum;
    ((float2*)out)[idx] = make_float2(o.x * inv, o.y * inv);
}

extern "C" void kernel_launch(void* const* d_in, const int* in_sizes, int n_in,
                              void* d_out, int out_size)
{
    const float* xr  = (const float*)d_in[0];
    const float* xi  = (const float*)d_in[1];
    const float* Wqr = (const float*)d_in[2];
    const float* Wqi = (const float*)d_in[3];
    const float* bqr = (const float*)d_in[4];
    const float* bqi = (const float*)d_in[5];
    const float* Wkr = (const float*)d_in[6];
    const float* Wki = (const float*)d_in[7];
    const float* bkr = (const float*)d_in[8];
    const float* bki = (const float*)d_in[9];
    const float* Wvr = (const float*)d_in[10];
    const float* Wvi = (const float*)d_in[11];
    const float* bvr = (const float*)d_in[12];
    const float* bvi = (const float*)d_in[13];

    cudaFuncSetAttribute(attn_partial_kernel,
                         cudaFuncAttributeMaxDynamicSharedMemorySize, ATTN_SMEM);

    dim3 pb(256), pg(HIDDEN / 64, MROWS / 64, 3);  // (8, 64, 3)
    proj_kernel<<<pg, pb>>>(xr, xi,
                            Wqr, Wqi, bqr, bqi,
                            Wkr, Wki, bkr, bki,
                            Wvr, Wvi, bvr, bvi);

    dim3 ag(NSEQ / 64, BHN, KSPLIT);               // (32, 16, 4) = 2048 CTAs
    attn_partial_kernel<<<ag, 256, ATTN_SMEM>>>();

    const size_t n_complex = (size_t)MROWS * HIDDEN;          // 2M
    reduce_kernel<<<(unsigned)(n_complex / 256), 256>>>((float*)d_out);
}

// round 15
// speedup vs baseline: 1.1706x; 1.0302x over previous
#include <cuda_runtime.h>
#include <cstdint>
#include <math.h>

#define HIDDEN 512
#define HEADS  8
#define DK     64
#define BATCH  2
#define NSEQ   2048
#define MROWS  (BATCH*NSEQ)     // 4096
#define BHN    (BATCH*HEADS)    // 16
#define NORMC  0.125f
#define TK     32               // keys per attention tile
#define KSPLIT 4                // key-range splits
#define NTILE_S (NSEQ/TK/KSPLIT)   // 16 key tiles per split CTA

typedef unsigned long long ull;
typedef unsigned int uint32;

// ---- packed f32x2 helpers (Blackwell FFMA2 path) ----
__device__ __forceinline__ ull bcast2(float x) {
    ull r; asm("mov.b64 %0, {%1,%1};" : "=l"(r) : "f"(x)); return r;
}
__device__ __forceinline__ float2 unpack2(ull v) {
    float2 f; asm("mov.b64 {%0,%1}, %2;" : "=f"(f.x), "=f"(f.y) : "l"(v)); return f;
}
__device__ __forceinline__ ull ffma2(ull a, ull b, ull c) {
    ull d; asm("fma.rn.f32x2 %0, %1, %2, %3;" : "=l"(d) : "l"(a), "l"(b), "l"(c)); return d;
}
__device__ __forceinline__ ull as_ull(float2 v) {
    ull r; asm("mov.b64 %0, {%1,%2};" : "=l"(r) : "f"(v.x), "f"(v.y)); return r;
}
__device__ __forceinline__ uint32 smem_u32(const void* p) {
    return (uint32)__cvta_generic_to_shared(p);
}
__device__ __forceinline__ void cpa16(uint32 dst, const void* src) {
    asm volatile("cp.async.cg.shared.global [%0], [%1], 16;" :: "r"(dst), "l"(src));
}
#define CPA_COMMIT() asm volatile("cp.async.commit_group;")
#define CPA_WAIT(n)  asm volatile("cp.async.wait_group %0;" :: "n"(n))

// Scratch: Q/K/V in [b,h,n,d] layout, complex interleaved (16B-aligned).
__device__ float4 g_q[(size_t)BHN * NSEQ * DK / 2];
__device__ float4 g_k[(size_t)BHN * NSEQ * DK / 2];
__device__ float4 g_v[(size_t)BHN * NSEQ * DK / 2];
// Split-KV partials: raw O and denominators.
__device__ float4 g_po[(size_t)KSPLIT * BHN * NSEQ * DK / 2];
__device__ float  g_pden[(size_t)KSPLIT * BHN * NSEQ];

// ---------------------------------------------------------------------------
// Projection (R11 calibrated version, ~70% of FFMA2 peak): Y = X @ W^T + b,
// FFMA2 inner loop, all 3 projections via blockIdx.z, register
// double-buffered global loads, single smem buffer.
// ---------------------------------------------------------------------------
__global__ __launch_bounds__(256, 2) void proj_kernel(
    const float* __restrict__ xr, const float* __restrict__ xi,
    const float* __restrict__ Wqr, const float* __restrict__ Wqi,
    const float* __restrict__ bqr, const float* __restrict__ bqi,
    const float* __restrict__ Wkr, const float* __restrict__ Wki,
    const float* __restrict__ bkr, const float* __restrict__ bki,
    const float* __restrict__ Wvr, const float* __restrict__ Wvi,
    const float* __restrict__ bvr, const float* __restrict__ bvi)
{
    __shared__ float2 Asc[64][17];
    __shared__ float2 Bsc[64][17];

    const int which = blockIdx.z;
    const float* Wr = (which == 0) ? Wqr : ((which == 1) ? Wkr : Wvr);
    const float* Wi = (which == 0) ? Wqi : ((which == 1) ? Wki : Wvi);
    const float* br = (which == 0) ? bqr : ((which == 1) ? bkr : bvr);
    const float* bi = (which == 0) ? bqi : ((which == 1) ? bki : bvi);
    float2* out = (float2*)((which == 0) ? g_q : ((which == 1) ? g_k : g_v));

    const int n0 = blockIdx.x * 64;
    const int m0 = blockIdx.y * 64;
    const int tid = threadIdx.x;
    const int tx = tid & 15, ty = tid >> 4;

    const int kk_s = tid & 15;
    const int rr0  = tid >> 4;

    float2 ra[4], rb[4];
    #pragma unroll
    for (int l = 0; l < 4; l++) {
        int rr = rr0 + l * 16;
        size_t ga = (size_t)(m0 + rr) * HIDDEN + kk_s;
        size_t gb = (size_t)(n0 + rr) * HIDDEN + kk_s;
        ra[l] = make_float2(xr[ga], xi[ga]);
        rb[l] = make_float2(Wr[gb], Wi[gb]);
    }

    ull acc1[4][4], acc2[4][4];
    #pragma unroll
    for (int i = 0; i < 4; i++)
        #pragma unroll
        for (int j = 0; j < 4; j++) { acc1[i][j] = 0ULL; acc2[i][j] = 0ULL; }

    for (int k0 = 0; k0 < HIDDEN; k0 += 16) {
        #pragma unroll
        for (int l = 0; l < 4; l++) {
            Asc[rr0 + l*16][kk_s] = ra[l];
            Bsc[rr0 + l*16][kk_s] = rb[l];
        }
        __syncthreads();

        if (k0 + 16 < HIDDEN) {
            #pragma unroll
            for (int l = 0; l < 4; l++) {
                int rr = rr0 + l * 16;
                size_t ga = (size_t)(m0 + rr) * HIDDEN + k0 + 16 + kk_s;
                size_t gb = (size_t)(n0 + rr) * HIDDEN + k0 + 16 + kk_s;
                ra[l] = make_float2(xr[ga], xi[ga]);
                rb[l] = make_float2(Wr[gb], Wi[gb]);
            }
        }

        #pragma unroll
        for (int kk = 0; kk < 16; kk++) {
            ull arr[4], aii[4], w2[4];
            #pragma unroll
            for (int i = 0; i < 4; i++) {
                float2 a = Asc[ty + 16*i][kk];
                arr[i] = bcast2(a.x); aii[i] = bcast2(a.y);
            }
            #pragma unroll
            for (int j = 0; j < 4; j++) w2[j] = as_ull(Bsc[tx + 16*j][kk]);
            #pragma unroll
            for (int i = 0; i < 4; i++)
                #pragma unroll
                for (int j = 0; j < 4; j++) {
                    acc1[i][j] = ffma2(arr[i], w2[j], acc1[i][j]);
                    acc2[i][j] = ffma2(aii[i], w2[j], acc2[i][j]);
                }
        }
        __syncthreads();
    }

    #pragma unroll
    for (int i = 0; i < 4; i++) {
        int m = m0 + ty + 16*i;
        int bb = m >> 11;
        int n  = m & 2047;
        #pragma unroll
        for (int j = 0; j < 4; j++) {
            int col = n0 + tx + 16*j;
            int h = col >> 6, d = col & 63;
            float2 c1 = unpack2(acc1[i][j]), c2 = unpack2(acc2[i][j]);
            float yr = c1.x - c2.y + br[col];
            float yi = c1.y + c2.x + bi[col];
            out[(((size_t)bb * HEADS + h) * NSEQ + n) * DK + d] = make_float2(yr, yi);
        }
    }
}

// ---------------------------------------------------------------------------
// Attention partial (split-KV), R11 layout. Barrier diet: the exp->PV
// hand-off of Ps is WARP-LOCAL (row ty+16i written and read by threads with
// the same ty, which live in one warp) -> __syncwarp instead of
// __syncthreads. 2 full barriers per tile (cp.async visibility + buffer
// reuse), was 3.
// ---------------------------------------------------------------------------
#define KS_STRIDE 33
#define KS_BUF    (32*KS_STRIDE)
#define VS_BUF    (32*64)
#define VS_BUF_BYTES (VS_BUF*8)
#define ATTN_SMEM (32768 + 33792 + 32768 + 8448)

__global__ __launch_bounds__(256, 2) void attn_partial_kernel()
{
    extern __shared__ float smem[];
    float4* Qs = (float4*)smem;                    // [64][32]
    float4* Ks = Qs + 64*32;                       // [2][32][KS_STRIDE]
    float2* Vs = (float2*)(Ks + 2*KS_BUF);         // [2][32][64]
    float*  Ps = (float*)(Vs + 2*VS_BUF);          // [64][33]

    const int bh = blockIdx.y;
    const int n0 = blockIdx.x * 64;
    const int sp = blockIdx.z;
    const int tid = threadIdx.x;
    const int tx = tid & 15, ty = tid >> 4;

    const float4* qb4 = g_q + ((size_t)bh * NSEQ + n0) * (DK/2);
    const float4* kb4 = g_k + (size_t)bh * NSEQ * (DK/2) + (size_t)sp * NTILE_S * 1024;
    const float4* vb4 = g_v + (size_t)bh * NSEQ * (DK/2) + (size_t)sp * NTILE_S * 1024;

    const uint32 qs_b = smem_u32(Qs);
    const uint32 ks_b = smem_u32(Ks);
    const uint32 vs_b = smem_u32(Vs);

    #pragma unroll
    for (int l = 0; l < 8; l++) {
        int id = tid + l * 256;
        cpa16(qs_b + id * 16, qb4 + id);
    }
    #pragma unroll
    for (int l = 0; l < 4; l++) {
        int id = tid + l * 256;
        int row = id >> 5, dp = id & 31;
        cpa16(ks_b + (row * KS_STRIDE + dp) * 16, kb4 + row * 32 + dp);
        cpa16(vs_b + id * 16, vb4 + id);
    }
    CPA_COMMIT();

    ull o_acc[4][4];
    #pragma unroll
    for (int i = 0; i < 4; i++)
        #pragma unroll
        for (int j = 0; j < 4; j++) o_acc[i][j] = 0ULL;
    float den[4] = {};

    for (int t = 0; t < NTILE_S; t++) {
        const int cur = t & 1;
        if (t + 1 < NTILE_S) {
            const int nb = cur ^ 1;
            const float4* kt = kb4 + (size_t)(t + 1) * 1024;
            const float4* vt = vb4 + (size_t)(t + 1) * 1024;
            #pragma unroll
            for (int l = 0; l < 4; l++) {
                int id = tid + l * 256;
                int row = id >> 5, dp = id & 31;
                cpa16(ks_b + (nb * KS_BUF + row * KS_STRIDE + dp) * 16, kt + row * 32 + dp);
                cpa16(vs_b + nb * VS_BUF_BYTES + id * 16, vt + id);
            }
            CPA_COMMIT();
            CPA_WAIT(1);
        } else {
            CPA_WAIT(0);
        }
        __syncthreads();

        // ---- S = Q . K^T (complex, no conj) over 32 keys ----
        ull s1[4][2], s2[4][2];
        #pragma unroll
        for (int i = 0; i < 4; i++)
            #pragma unroll
            for (int j = 0; j < 2; j++) { s1[i][j] = 0ULL; s2[i][j] = 0ULL; }

        const longlong2* Ksc = (const longlong2*)(Ks + cur * KS_BUF);
        const longlong2* Qsc = (const longlong2*)Qs;

        #pragma unroll 4
        for (int dp = 0; dp < 32; dp++) {
            longlong2 q2[4];
            #pragma unroll
            for (int i = 0; i < 4; i++) q2[i] = Qsc[(ty + 16*i) * 32 + dp];

            ull kxx[2][2], kyy[2][2];
            #pragma unroll
            for (int j = 0; j < 2; j++) {
                longlong2 kv = Ksc[(tx + 16*j) * KS_STRIDE + dp];
                float2 k0 = unpack2((ull)kv.x), k1 = unpack2((ull)kv.y);
                kxx[j][0] = bcast2(k0.x); kyy[j][0] = bcast2(k0.y);
                kxx[j][1] = bcast2(k1.x); kyy[j][1] = bcast2(k1.y);
            }
            #pragma unroll
            for (int i = 0; i < 4; i++)
                #pragma unroll
                for (int j = 0; j < 2; j++) {
                    s1[i][j] = ffma2((ull)q2[i].x, kxx[j][0], s1[i][j]);
                    s2[i][j] = ffma2((ull)q2[i].x, kyy[j][0], s2[i][j]);
                    s1[i][j] = ffma2((ull)q2[i].y, kxx[j][1], s1[i][j]);
                    s2[i][j] = ffma2((ull)q2[i].y, kyy[j][1], s2[i][j]);
                }
        }

        // ---- w = exp(|s|*NORM) -> Ps (warp-local hand-off) ----
        #pragma unroll
        for (int i = 0; i < 4; i++)
            #pragma unroll
            for (int j = 0; j < 2; j++) {
                float2 c1 = unpack2(s1[i][j]), c2 = unpack2(s2[i][j]);
                float sr = c1.x - c2.y;
                float si = c1.y + c2.x;
                float a = sqrtf(sr * sr + si * si) * NORMC;
                float w = __expf(a);
                den[i] += w;
                Ps[(ty + 16*i) * 33 + (tx + 16*j)] = w;
            }
        __syncwarp();   // P rows are produced+consumed within one warp

        // ---- O += P @ V ----
        const float2* Vsc = Vs + cur * VS_BUF;
        #pragma unroll 4
        for (int c = 0; c < 32; c++) {
            ull p2[4], vv[4];
            #pragma unroll
            for (int i = 0; i < 4; i++) p2[i] = bcast2(Ps[(ty + 16*i) * 33 + c]);
            #pragma unroll
            for (int j = 0; j < 4; j++) vv[j] = as_ull(Vsc[c * 64 + tx + 16*j]);
            #pragma unroll
            for (int i = 0; i < 4; i++)
                #pragma unroll
                for (int j = 0; j < 4; j++)
                    o_acc[i][j] = ffma2(p2[i], vv[j], o_acc[i][j]);
        }
        __syncthreads();   // all reads of buffer `cur` done before re-fill
    }

    #pragma unroll
    for (int i = 0; i < 4; i++) Ps[(ty + 16*i) * 17 + tx] = den[i];
    __syncthreads();
    #pragma unroll
    for (int i = 0; i < 4; i++) {
        float s = 0.f;
        #pragma unroll
        for (int tt = 0; tt < 16; tt++) s += Ps[(ty + 16*i) * 17 + tt];
        den[i] = s;
    }

    float2* po = (float2*)g_po + (((size_t)sp * BHN + bh) * NSEQ + n0) * DK;
    float*  pd = g_pden + ((size_t)sp * BHN + bh) * NSEQ + n0;

    #pragma unroll
    for (int i = 0; i < 4; i++) {
        int nl = ty + 16*i;
        if (tx == 0) pd[nl] = den[i];
        #pragma unroll
        for (int j = 0; j < 4; j++) {
            int d = tx + 16*j;
            po[(size_t)nl * DK + d] = unpack2(o_acc[i][j]);
        }
    }
}

// ---------------------------------------------------------------------------
// Combine: out = sum_s o_s / sum_s den_s. Output layout [B,N,D,2].
// ---------------------------------------------------------------------------
__global__ __launch_bounds__(256) void reduce_kernel(float* __restrict__ out)
{
    const size_t idx = (size_t)blockIdx.x * 256 + threadIdx.x;
    const int d  = idx & 63;
    const int h  = (int)((idx >> 6) & 7);
    const int n  = (int)((idx >> 9) & 2047);
    const int b  = (int)(idx >> 20);
    const int bh = b * HEADS + h;

    const float2* po2 = (const float2*)g_po;
    float2 o = make_float2(0.f, 0.f);
    float dsum = 0.f;
    #pragma unroll
    for (int s = 0; s < KSPLIT; s++) {
        float2 p = po2[(((size_t)s * BHN + bh) * NSEQ + n) * DK + d];
        o.x += p.x; o.y += p.y;
        dsum += g_pden[((size_t)s * BHN + bh) * NSEQ + n];
    }
    float inv = 1.0f / dsum;
    ((float2*)out)[idx] = make_float2(o.x * inv, o.y * inv);
}

extern "C" void kernel_launch(void* const* d_in, const int* in_sizes, int n_in,
                              void* d_out, int out_size)
{
    const float* xr  = (const float*)d_in[0];
    const float* xi  = (const float*)d_in[1];
    const float* Wqr = (const float*)d_in[2];
    const float* Wqi = (const float*)d_in[3];
    const float* bqr = (const float*)d_in[4];
    const float* bqi = (const float*)d_in[5];
    const float* Wkr = (const float*)d_in[6];
    const float* Wki = (const float*)d_in[7];
    const float* bkr = (const float*)d_in[8];
    const float* bki = (const float*)d_in[9];
    const float* Wvr = (const float*)d_in[10];
    const float* Wvi = (const float*)d_in[11];
    const float* bvr = (const float*)d_in[12];
    const float* bvi = (const float*)d_in[13];

    cudaFuncSetAttribute(attn_partial_kernel,
                         cudaFuncAttributeMaxDynamicSharedMemorySize, ATTN_SMEM);

    dim3 pb(256), pg(HIDDEN / 64, MROWS / 64, 3);  // (8, 64, 3)
    proj_kernel<<<pg, pb>>>(xr, xi,
                            Wqr, Wqi, bqr, bqi,
                            Wkr, Wki, bkr, bki,
                            Wvr, Wvi, bvr, bvi);

    dim3 ag(NSEQ / 64, BHN, KSPLIT);               // (32, 16, 4) = 2048 CTAs
    attn_partial_kernel<<<ag, 256, ATTN_SMEM>>>();

    const size_t n_complex = (size_t)MROWS * HIDDEN;          // 2M
    reduce_kernel<<<(unsigned)(n_complex / 256), 256>>>((float*)d_out);
}

// round 17
// speedup vs baseline: 1.4185x; 1.2117x over previous
#include <cuda_runtime.h>
#include <cuda_bf16.h>
#include <cstdint>
#include <math.h>

#define HIDDEN 512
#define HEADS  8
#define DK     64
#define BATCH  2
#define NSEQ   2048
#define MROWS  (BATCH*NSEQ)     // 4096
#define BHN    (BATCH*HEADS)    // 16
#define NORMC  0.125f
#define TK     32
#define KSPLIT 4
#define NTILE_S (NSEQ/TK/KSPLIT)   // 16

typedef unsigned long long ull;
typedef unsigned int uint32;

// ---- packed f32x2 helpers ----
__device__ __forceinline__ ull bcast2(float x) {
    ull r; asm("mov.b64 %0, {%1,%1};" : "=l"(r) : "f"(x)); return r;
}
__device__ __forceinline__ float2 unpack2(ull v) {
    float2 f; asm("mov.b64 {%0,%1}, %2;" : "=f"(f.x), "=f"(f.y) : "l"(v)); return f;
}
__device__ __forceinline__ ull ffma2(ull a, ull b, ull c) {
    ull d; asm("fma.rn.f32x2 %0, %1, %2, %3;" : "=l"(d) : "l"(a), "l"(b), "l"(c)); return d;
}
__device__ __forceinline__ ull as_ull(float2 v) {
    ull r; asm("mov.b64 %0, {%1,%2};" : "=l"(r) : "f"(v.x), "f"(v.y)); return r;
}
__device__ __forceinline__ uint32 smem_u32(const void* p) {
    return (uint32)__cvta_generic_to_shared(p);
}
__device__ __forceinline__ void cpa16(uint32 dst, const void* src) {
    asm volatile("cp.async.cg.shared.global [%0], [%1], 16;" :: "r"(dst), "l"(src));
}
#define CPA_COMMIT() asm volatile("cp.async.commit_group;")
#define CPA_WAIT(n)  asm volatile("cp.async.wait_group %0;" :: "n"(n))

// ---- mma.sync helpers (sm_80+ baseline features; work on plain sm_100) ----
__device__ __forceinline__ void ldsm_x4(uint32* r, uint32 addr) {
    asm volatile("ldmatrix.sync.aligned.m8n8.x4.shared.b16 {%0,%1,%2,%3}, [%4];"
        : "=r"(r[0]), "=r"(r[1]), "=r"(r[2]), "=r"(r[3]) : "r"(addr));
}
__device__ __forceinline__ void mma_bf16(float* c, const uint32* a, uint32 b0, uint32 b1) {
    asm volatile(
        "mma.sync.aligned.m16n8k16.row.col.f32.bf16.bf16.f32 "
        "{%0,%1,%2,%3}, {%4,%5,%6,%7}, {%8,%9}, {%0,%1,%2,%3};"
        : "+f"(c[0]), "+f"(c[1]), "+f"(c[2]), "+f"(c[3])
        : "r"(a[0]), "r"(a[1]), "r"(a[2]), "r"(a[3]), "r"(b0), "r"(b1));
}

// ---- device scratch ----
__device__ float4 g_q[(size_t)BHN * NSEQ * DK / 2];
__device__ float4 g_k[(size_t)BHN * NSEQ * DK / 2];
__device__ float4 g_v[(size_t)BHN * NSEQ * DK / 2];
__device__ float4 g_po[(size_t)KSPLIT * BHN * NSEQ * DK / 2];
__device__ float  g_pden[(size_t)KSPLIT * BHN * NSEQ];
// bf16 split: X -> 0=ar_hi 1=ar_lo 2=ai_hi 3=ai_lo
__device__ float4 g_axbuf[4][MROWS * HIDDEN / 8];
// W -> 0=wr_hi 1=wr_lo 2=wi_hi 3=wi_lo 4=-wi_hi 5=-wi_lo
__device__ float4 g_wbuf[3][6][HIDDEN * HIDDEN / 8];

// ---------------------------------------------------------------------------
// Conversion prepass: fp32 -> bf16 (hi, lo) split.
// ---------------------------------------------------------------------------
__global__ __launch_bounds__(256) void conv_x_kernel(
    const float* __restrict__ xr, const float* __restrict__ xi)
{
    const int idx = blockIdx.x * 256 + threadIdx.x;
    __nv_bfloat16* arh = (__nv_bfloat16*)g_axbuf[0];
    __nv_bfloat16* arl = (__nv_bfloat16*)g_axbuf[1];
    __nv_bfloat16* aih = (__nv_bfloat16*)g_axbuf[2];
    __nv_bfloat16* ail = (__nv_bfloat16*)g_axbuf[3];
    float v = xr[idx];
    __nv_bfloat16 h = __float2bfloat16(v);
    arh[idx] = h;
    arl[idx] = __float2bfloat16(v - __bfloat162float(h));
    v = xi[idx];
    h = __float2bfloat16(v);
    aih[idx] = h;
    ail[idx] = __float2bfloat16(v - __bfloat162float(h));
}

__global__ __launch_bounds__(256) void conv_w_kernel(
    const float* __restrict__ Wqr, const float* __restrict__ Wqi,
    const float* __restrict__ Wkr, const float* __restrict__ Wki,
    const float* __restrict__ Wvr, const float* __restrict__ Wvi)
{
    const int idx = blockIdx.x * 256 + threadIdx.x;
    const int which = idx >> 18;
    const int e = idx & 262143;
    const float* wr = (which == 0) ? Wqr : ((which == 1) ? Wkr : Wvr);
    const float* wi = (which == 0) ? Wqi : ((which == 1) ? Wki : Wvi);
    float vr = wr[e], vi = wi[e];
    __nv_bfloat16 rh = __float2bfloat16(vr);
    __nv_bfloat16 rl = __float2bfloat16(vr - __bfloat162float(rh));
    __nv_bfloat16 ih = __float2bfloat16(vi);
    __nv_bfloat16 il = __float2bfloat16(vi - __bfloat162float(ih));
    ((__nv_bfloat16*)g_wbuf[which][0])[e] = rh;
    ((__nv_bfloat16*)g_wbuf[which][1])[e] = rl;
    ((__nv_bfloat16*)g_wbuf[which][2])[e] = ih;
    ((__nv_bfloat16*)g_wbuf[which][3])[e] = il;
    ((__nv_bfloat16*)g_wbuf[which][4])[e] = __hneg(ih);
    ((__nv_bfloat16*)g_wbuf[which][5])[e] = __hneg(il);
}

// ---------------------------------------------------------------------------
// HMMA projection GEMM (mma.sync m16n8k16 bf16, 3-term split, complex folded
// into virtual K = 6 segs x 512):
//   A segs:  [ar_hi, ar_hi, ar_lo, ai_hi, ai_hi, ai_lo]
//   Bre segs:[wr_hi, wr_lo, wr_hi, -wi_hi, -wi_lo, -wi_hi]   -> D_re
//   Bim segs:[wi_hi, wi_lo, wi_hi,  wr_hi,  wr_lo,  wr_hi]   -> D_im
// CTA: 128M x 64N, 8 warps = 2M x 4N; each warp: 64x16 of BOTH re and im.
// Chunks of K=64, cp.async double buffer; XOR-swizzled tiles + ldmatrix.
// SMEM: 2 x (A 16K + Bre 8K + Bim 8K) = 64K. 2 CTAs/SM.
// ---------------------------------------------------------------------------
#define PROJ_SMEM 65536

__device__ __forceinline__ void proj_load_chunk(
    uint32 sb, int buf, int chunk, int m0, int n0, int which, int tid)
{
    const int seg = chunk >> 3;
    const int k0  = (chunk & 7) * 64;
    int aidx, bridx, biidx;
    switch (seg) {
        case 0:  aidx = 0; bridx = 0; biidx = 2; break;
        case 1:  aidx = 0; bridx = 1; biidx = 3; break;
        case 2:  aidx = 1; bridx = 0; biidx = 2; break;
        case 3:  aidx = 2; bridx = 4; biidx = 0; break;
        case 4:  aidx = 2; bridx = 5; biidx = 1; break;
        default: aidx = 3; bridx = 4; biidx = 0; break;
    }
    const char* ab  = (const char*)g_axbuf[aidx];
    const char* brb = (const char*)g_wbuf[which][bridx];
    const char* bib = (const char*)g_wbuf[which][biidx];
    const uint32 abase = sb + buf * 32768;
    const uint32 rbase = abase + 16384;
    const uint32 ibase = abase + 24576;
    #pragma unroll
    for (int t = 0; t < 4; t++) {               // A: 128 rows x 8 16B-cols
        int id = tid + t * 256;
        int row = id >> 3, c = id & 7;
        cpa16(abase + row * 128 + ((c ^ (row & 7)) * 16),
              ab + ((size_t)(m0 + row) * HIDDEN + k0 + c * 8) * 2);
    }
    #pragma unroll
    for (int t = 0; t < 2; t++) {               // Bre: 64 rows x 8
        int id = tid + t * 256;
        int row = id >> 3, c = id & 7;
        cpa16(rbase + row * 128 + ((c ^ (row & 7)) * 16),
              brb + ((size_t)(n0 + row) * HIDDEN + k0 + c * 8) * 2);
    }
    #pragma unroll
    for (int t = 0; t < 2; t++) {               // Bim
        int id = tid + t * 256;
        int row = id >> 3, c = id & 7;
        cpa16(ibase + row * 128 + ((c ^ (row & 7)) * 16),
              bib + ((size_t)(n0 + row) * HIDDEN + k0 + c * 8) * 2);
    }
}

__global__ __launch_bounds__(256, 2) void proj_mma_kernel(
    const float* __restrict__ bqr, const float* __restrict__ bqi,
    const float* __restrict__ bkr, const float* __restrict__ bki,
    const float* __restrict__ bvr, const float* __restrict__ bvi)
{
    extern __shared__ char psm[];
    const int which = blockIdx.z;
    const int n0 = blockIdx.x * 64;
    const int m0 = blockIdx.y * 128;
    const int tid = threadIdx.x;
    const int lane = tid & 31, wid = tid >> 5;
    const int wm = wid >> 2, wn = wid & 3;
    const uint32 sb = smem_u32(psm);

    // ldmatrix per-lane address components
    const int l7 = lane & 7;
    const uint32 aoff  = (uint32)(wm * 64 + l7 + ((lane >> 3) & 1) * 8) * 128;
    const uint32 acolx = (uint32)(lane >> 4);          // k-half select
    const uint32 boff  = (uint32)(wn * 16 + (lane >> 4) * 8 + l7) * 128;
    const uint32 bkh   = (uint32)((lane >> 3) & 1);

    float cre[4][2][4], cim[4][2][4];
    #pragma unroll
    for (int mt = 0; mt < 4; mt++)
        #pragma unroll
        for (int nt = 0; nt < 2; nt++)
            #pragma unroll
            for (int e = 0; e < 4; e++) { cre[mt][nt][e] = 0.f; cim[mt][nt][e] = 0.f; }

    proj_load_chunk(sb, 0, 0, m0, n0, which, tid);
    CPA_COMMIT();

    for (int c = 0; c < 48; c++) {
        const int cur = c & 1;
        if (c + 1 < 48) {
            proj_load_chunk(sb, cur ^ 1, c + 1, m0, n0, which, tid);
            CPA_COMMIT();
            CPA_WAIT(1);
        } else {
            CPA_WAIT(0);
        }
        __syncthreads();

        const uint32 abuf = sb + cur * 32768;
        const uint32 rbuf = abuf + 16384;
        const uint32 ibuf = abuf + 24576;

        #pragma unroll
        for (int ks = 0; ks < 4; ks++) {
            uint32 a[4][4];
            #pragma unroll
            for (int mt = 0; mt < 4; mt++)
                ldsm_x4(a[mt], abuf + aoff + mt * 2048 +
                               (((2u * ks + acolx) ^ (uint32)l7) * 16));
            uint32 brf[4], bif[4];
            ldsm_x4(brf, rbuf + boff + (((2u * ks + bkh) ^ (uint32)l7) * 16));
            ldsm_x4(bif, ibuf + boff + (((2u * ks + bkh) ^ (uint32)l7) * 16));
            #pragma unroll
            for (int mt = 0; mt < 4; mt++)
                #pragma unroll
                for (int nt = 0; nt < 2; nt++) {
                    mma_bf16(cre[mt][nt], a[mt], brf[nt*2], brf[nt*2+1]);
                    mma_bf16(cim[mt][nt], a[mt], bif[nt*2], bif[nt*2+1]);
                }
        }
        __syncthreads();
    }

    const float* br = (which == 0) ? bqr : ((which == 1) ? bkr : bvr);
    const float* bi = (which == 0) ? bqi : ((which == 1) ? bki : bvi);
    float2* out = (float2*)((which == 0) ? g_q : ((which == 1) ? g_k : g_v));

    #pragma unroll
    for (int mt = 0; mt < 4; mt++) {
        #pragma unroll
        for (int nt = 0; nt < 2; nt++) {
            int col = n0 + wn * 16 + nt * 8 + (lane & 3) * 2;
            int h = col >> 6, d = col & 63;
            float brc0 = br[col], bic0 = bi[col];
            float brc1 = br[col + 1], bic1 = bi[col + 1];
            int r1 = m0 + wm * 64 + mt * 16 + (lane >> 2);
            int r2 = r1 + 8;
            {
                int b = r1 >> 11, n = r1 & 2047;
                float4 v = make_float4(cre[mt][nt][0] + brc0, cim[mt][nt][0] + bic0,
                                       cre[mt][nt][1] + brc1, cim[mt][nt][1] + bic1);
                *(float4*)&out[(((size_t)b * HEADS + h) * NSEQ + n) * DK + d] = v;
            }
            {
                int b = r2 >> 11, n = r2 & 2047;
                float4 v = make_float4(cre[mt][nt][2] + brc0, cim[mt][nt][2] + bic0,
                                       cre[mt][nt][3] + brc1, cim[mt][nt][3] + bic1);
                *(float4*)&out[(((size_t)b * HEADS + h) * NSEQ + n) * DK + d] = v;
            }
        }
    }
}

// ---------------------------------------------------------------------------
// Attention partial (split-KV) — unchanged R15 version (calibrated).
// ---------------------------------------------------------------------------
#define KS_STRIDE 33
#define KS_BUF    (32*KS_STRIDE)
#define VS_BUF    (32*64)
#define VS_BUF_BYTES (VS_BUF*8)
#define ATTN_SMEM (32768 + 33792 + 32768 + 8448)

__global__ __launch_bounds__(256, 2) void attn_partial_kernel()
{
    extern __shared__ float smem[];
    float4* Qs = (float4*)smem;
    float4* Ks = Qs + 64*32;
    float2* Vs = (float2*)(Ks + 2*KS_BUF);
    float*  Ps = (float*)(Vs + 2*VS_BUF);

    const int bh = blockIdx.y;
    const int n0 = blockIdx.x * 64;
    const int sp = blockIdx.z;
    const int tid = threadIdx.x;
    const int tx = tid & 15, ty = tid >> 4;

    const float4* qb4 = g_q + ((size_t)bh * NSEQ + n0) * (DK/2);
    const float4* kb4 = g_k + (size_t)bh * NSEQ * (DK/2) + (size_t)sp * NTILE_S * 1024;
    const float4* vb4 = g_v + (size_t)bh * NSEQ * (DK/2) + (size_t)sp * NTILE_S * 1024;

    const uint32 qs_b = smem_u32(Qs);
    const uint32 ks_b = smem_u32(Ks);
    const uint32 vs_b = smem_u32(Vs);

    #pragma unroll
    for (int l = 0; l < 8; l++) {
        int id = tid + l * 256;
        cpa16(qs_b + id * 16, qb4 + id);
    }
    #pragma unroll
    for (int l = 0; l < 4; l++) {
        int id = tid + l * 256;
        int row = id >> 5, dp = id & 31;
        cpa16(ks_b + (row * KS_STRIDE + dp) * 16, kb4 + row * 32 + dp);
        cpa16(vs_b + id * 16, vb4 + id);
    }
    CPA_COMMIT();

    ull o_acc[4][4];
    #pragma unroll
    for (int i = 0; i < 4; i++)
        #pragma unroll
        for (int j = 0; j < 4; j++) o_acc[i][j] = 0ULL;
    float den[4] = {};

    for (int t = 0; t < NTILE_S; t++) {
        const int cur = t & 1;
        if (t + 1 < NTILE_S) {
            const int nb = cur ^ 1;
            const float4* kt = kb4 + (size_t)(t + 1) * 1024;
            const float4* vt = vb4 + (size_t)(t + 1) * 1024;
            #pragma unroll
            for (int l = 0; l < 4; l++) {
                int id = tid + l * 256;
                int row = id >> 5, dp = id & 31;
                cpa16(ks_b + (nb * KS_BUF + row * KS_STRIDE + dp) * 16, kt + row * 32 + dp);
                cpa16(vs_b + nb * VS_BUF_BYTES + id * 16, vt + id);
            }
            CPA_COMMIT();
            CPA_WAIT(1);
        } else {
            CPA_WAIT(0);
        }
        __syncthreads();

        ull s1[4][2], s2[4][2];
        #pragma unroll
        for (int i = 0; i < 4; i++)
            #pragma unroll
            for (int j = 0; j < 2; j++) { s1[i][j] = 0ULL; s2[i][j] = 0ULL; }

        const longlong2* Ksc = (const longlong2*)(Ks + cur * KS_BUF);
        const longlong2* Qsc = (const longlong2*)Qs;

        #pragma unroll 4
        for (int dp = 0; dp < 32; dp++) {
            longlong2 q2[4];
            #pragma unroll
            for (int i = 0; i < 4; i++) q2[i] = Qsc[(ty + 16*i) * 32 + dp];

            ull kxx[2][2], kyy[2][2];
            #pragma unroll
            for (int j = 0; j < 2; j++) {
                longlong2 kv = Ksc[(tx + 16*j) * KS_STRIDE + dp];
                float2 k0 = unpack2((ull)kv.x), k1 = unpack2((ull)kv.y);
                kxx[j][0] = bcast2(k0.x); kyy[j][0] = bcast2(k0.y);
                kxx[j][1] = bcast2(k1.x); kyy[j][1] = bcast2(k1.y);
            }
            #pragma unroll
            for (int i = 0; i < 4; i++)
                #pragma unroll
                for (int j = 0; j < 2; j++) {
                    s1[i][j] = ffma2((ull)q2[i].x, kxx[j][0], s1[i][j]);
                    s2[i][j] = ffma2((ull)q2[i].x, kyy[j][0], s2[i][j]);
                    s1[i][j] = ffma2((ull)q2[i].y, kxx[j][1], s1[i][j]);
                    s2[i][j] = ffma2((ull)q2[i].y, kyy[j][1], s2[i][j]);
                }
        }

        #pragma unroll
        for (int i = 0; i < 4; i++)
            #pragma unroll
            for (int j = 0; j < 2; j++) {
                float2 c1 = unpack2(s1[i][j]), c2 = unpack2(s2[i][j]);
                float sr = c1.x - c2.y;
                float si = c1.y + c2.x;
                float a = sqrtf(sr * sr + si * si) * NORMC;
                float w = __expf(a);
                den[i] += w;
                Ps[(ty + 16*i) * 33 + (tx + 16*j)] = w;
            }
        __syncwarp();

        const float2* Vsc = Vs + cur * VS_BUF;
        #pragma unroll 4
        for (int c = 0; c < 32; c++) {
            ull p2[4], vv[4];
            #pragma unroll
            for (int i = 0; i < 4; i++) p2[i] = bcast2(Ps[(ty + 16*i) * 33 + c]);
            #pragma unroll
            for (int j = 0; j < 4; j++) vv[j] = as_ull(Vsc[c * 64 + tx + 16*j]);
            #pragma unroll
            for (int i = 0; i < 4; i++)
                #pragma unroll
                for (int j = 0; j < 4; j++)
                    o_acc[i][j] = ffma2(p2[i], vv[j], o_acc[i][j]);
        }
        __syncthreads();
    }

    #pragma unroll
    for (int i = 0; i < 4; i++) Ps[(ty + 16*i) * 17 + tx] = den[i];
    __syncthreads();
    #pragma unroll
    for (int i = 0; i < 4; i++) {
        float s = 0.f;
        #pragma unroll
        for (int tt = 0; tt < 16; tt++) s += Ps[(ty + 16*i) * 17 + tt];
        den[i] = s;
    }

    float2* po = (float2*)g_po + (((size_t)sp * BHN + bh) * NSEQ + n0) * DK;
    float*  pd = g_pden + ((size_t)sp * BHN + bh) * NSEQ + n0;

    #pragma unroll
    for (int i = 0; i < 4; i++) {
        int nl = ty + 16*i;
        if (tx == 0) pd[nl] = den[i];
        #pragma unroll
        for (int j = 0; j < 4; j++) {
            int d = tx + 16*j;
            po[(size_t)nl * DK + d] = unpack2(o_acc[i][j]);
        }
    }
}

// ---------------------------------------------------------------------------
// Combine partials. Output layout [B,N,D,2].
// ---------------------------------------------------------------------------
__global__ __launch_bounds__(256) void reduce_kernel(float* __restrict__ out)
{
    const size_t idx = (size_t)blockIdx.x * 256 + threadIdx.x;
    const int d  = idx & 63;
    const int h  = (int)((idx >> 6) & 7);
    const int n  = (int)((idx >> 9) & 2047);
    const int b  = (int)(idx >> 20);
    const int bh = b * HEADS + h;

    const float2* po2 = (const float2*)g_po;
    float2 o = make_float2(0.f, 0.f);
    float dsum = 0.f;
    #pragma unroll
    for (int s = 0; s < KSPLIT; s++) {
        float2 p = po2[(((size_t)s * BHN + bh) * NSEQ + n) * DK + d];
        o.x += p.x; o.y += p.y;
        dsum += g_pden[((size_t)s * BHN + bh) * NSEQ + n];
    }
    float inv = 1.0f / dsum;
    ((float2*)out)[idx] = make_float2(o.x * inv, o.y * inv);
}

extern "C" void kernel_launch(void* const* d_in, const int* in_sizes, int n_in,
                              void* d_out, int out_size)
{
    const float* xr  = (const float*)d_in[0];
    const float* xi  = (const float*)d_in[1];
    const float* Wqr = (const float*)d_in[2];
    const float* Wqi = (const float*)d_in[3];
    const float* bqr = (const float*)d_in[4];
    const float* bqi = (const float*)d_in[5];
    const float* Wkr = (const float*)d_in[6];
    const float* Wki = (const float*)d_in[7];
    const float* bkr = (const float*)d_in[8];
    const float* bki = (const float*)d_in[9];
    const float* Wvr = (const float*)d_in[10];
    const float* Wvi = (const float*)d_in[11];
    const float* bvr = (const float*)d_in[12];
    const float* bvi = (const float*)d_in[13];

    cudaFuncSetAttribute(proj_mma_kernel,
                         cudaFuncAttributeMaxDynamicSharedMemorySize, PROJ_SMEM);
    cudaFuncSetAttribute(attn_partial_kernel,
                         cudaFuncAttributeMaxDynamicSharedMemorySize, ATTN_SMEM);

    conv_x_kernel<<<MROWS * HIDDEN / 256, 256>>>(xr, xi);
    conv_w_kernel<<<3 * HIDDEN * HIDDEN / 256, 256>>>(Wqr, Wqi, Wkr, Wki, Wvr, Wvi);

    dim3 pg(HIDDEN / 64, MROWS / 128, 3);          // (8, 32, 3) = 768 CTAs
    proj_mma_kernel<<<pg, 256, PROJ_SMEM>>>(bqr, bqi, bkr, bki, bvr, bvi);

    dim3 ag(NSEQ / 64, BHN, KSPLIT);               // (32, 16, 4) = 2048 CTAs
    attn_partial_kernel<<<ag, 256, ATTN_SMEM>>>();

    const size_t n_complex = (size_t)MROWS * HIDDEN;
    reduce_kernel<<<(unsigned)(n_complex / 256), 256>>>((float*)d_out);
}